// round 16
// baseline (speedup 1.0000x reference)
#include <cuda_runtime.h>
#include <cuda_bf16.h>
#include <cuda_fp16.h>
#include <cstdint>

#define BB 256
#define TT 256
#define EMB 384
#define HH 6
#define DD 64
#define BT (BB*TT)

// ---------------------------------------------------------------------------
// Scratch (__device__ globals — allocation-free rule).  Pure fp16 pipeline.
// ---------------------------------------------------------------------------
__device__ __align__(16) __half g_qhi[BB * HH * TT * DD];
__device__ __align__(16) __half g_khi[BB * HH * TT * DD];
__device__ __align__(16) __half g_vhi[BB * HH * TT * DD];
__device__ __align__(16) __half g_xhi[BT * EMB];
__device__ __align__(16) __half g_wthi[3 * HH * DD * EMB];  // [n=z*384+h*64+d][e]
__device__ __align__(16) __half g_wphi[EMB * EMB];          // [n][k]
__device__ __align__(16) __half g_atthi[BT * EMB];

// ---------------------------------------------------------------------------
// mma.sync / ldmatrix / cp.async helpers
// ---------------------------------------------------------------------------
__device__ __forceinline__ uint32_t smem_u32(const void* p) {
    uint32_t a;
    asm("{ .reg .u64 t; cvta.to.shared.u64 t, %1; cvt.u32.u64 %0, t; }"
        : "=r"(a) : "l"(p));
    return a;
}
__device__ __forceinline__ void ldm4(uint32_t* r, uint32_t addr) {
    asm volatile("ldmatrix.sync.aligned.m8n8.x4.shared.b16 {%0,%1,%2,%3}, [%4];"
        : "=r"(r[0]), "=r"(r[1]), "=r"(r[2]), "=r"(r[3]) : "r"(addr));
}
__device__ __forceinline__ void ldm4t(uint32_t* r, uint32_t addr) {
    asm volatile("ldmatrix.sync.aligned.m8n8.x4.trans.shared.b16 {%0,%1,%2,%3}, [%4];"
        : "=r"(r[0]), "=r"(r[1]), "=r"(r[2]), "=r"(r[3]) : "r"(addr));
}
__device__ __forceinline__ void mma_f16(float* c, const uint32_t* a, const uint32_t* b) {
    asm volatile(
        "mma.sync.aligned.m16n8k16.row.col.f32.f16.f16.f32 "
        "{%0,%1,%2,%3}, {%4,%5,%6,%7}, {%8,%9}, {%0,%1,%2,%3};"
        : "+f"(c[0]), "+f"(c[1]), "+f"(c[2]), "+f"(c[3])
        : "r"(a[0]), "r"(a[1]), "r"(a[2]), "r"(a[3]), "r"(b[0]), "r"(b[1]));
}
__device__ __forceinline__ void cp16(uint32_t dst, const void* src) {
    asm volatile("cp.async.cg.shared.global [%0], [%1], 16;" :: "r"(dst), "l"(src));
}
#define CP_COMMIT() asm volatile("cp.async.commit_group;" ::: "memory")
#define CP_WAIT_1() asm volatile("cp.async.wait_group 1;" ::: "memory")
#define CP_WAIT_ALL() asm volatile("cp.async.wait_group 0;" ::: "memory")

__device__ __forceinline__ uint32_t pack_h2(float lo, float hi) {
    __half2 h = __floats2half2_rn(lo, hi);
    return *(uint32_t*)&h;
}

// 128B-row tile swizzle (8 units of 16B): u ^ (r&7)
__device__ __forceinline__ uint32_t swz8(uint32_t r, uint32_t u) {
    return (r << 7) + ((u ^ (r & 7u)) << 4);
}

// ---------------------------------------------------------------------------
// Prep kernels — all memory-coalesced.
// 1) x -> fp16 (float4 vectorized)
// 2) wq/wk/wv transpose [h][e][d] -> [zh][d][e] via 32x32 smem tiles
// 3) w_proj transpose [k][n] -> [n][k] via 32x32 smem tiles
// ---------------------------------------------------------------------------
#define NX   (BT * EMB)
#define NX4  (NX / 4)

__global__ void prep_x(const float* __restrict__ x) {
    int i = blockIdx.x * 256 + threadIdx.x;
    if (i < NX4) {
        float4 f = *(const float4*)(x + (size_t)i * 4);
        uint32_t p0 = pack_h2(f.x, f.y);
        uint32_t p1 = pack_h2(f.z, f.w);
        *(uint2*)(g_xhi + (size_t)i * 4) = make_uint2(p0, p1);
    }
}

// grid (12, 2, 18), block (32, 32): transpose 384x64 per (z,h)
__global__ void prep_wqkv(const float* __restrict__ wq, const float* __restrict__ wk,
                          const float* __restrict__ wv) {
    __shared__ float ts[32][33];
    const int zh = blockIdx.z;
    const int z = zh / HH, h = zh % HH;
    const int e0 = blockIdx.x * 32;
    const int d0 = blockIdx.y * 32;
    const int tx = threadIdx.x, ty = threadIdx.y;
    const float* w = ((z == 0) ? wq : (z == 1) ? wk : wv) + (size_t)h * EMB * DD;

    ts[ty][tx] = w[(size_t)(e0 + ty) * DD + d0 + tx];      // coalesced read (d contiguous)
    __syncthreads();
    g_wthi[(size_t)zh * DD * EMB + (size_t)(d0 + ty) * EMB + e0 + tx] =
        __float2half(ts[tx][ty]);                          // coalesced write (e contiguous)
}

// grid (12, 12), block (32, 32): transpose 384x384
__global__ void prep_wpk(const float* __restrict__ wp) {
    __shared__ float ts[32][33];
    const int k0 = blockIdx.x * 32;
    const int n0 = blockIdx.y * 32;
    const int tx = threadIdx.x, ty = threadIdx.y;

    ts[ty][tx] = wp[(size_t)(k0 + ty) * EMB + n0 + tx];    // coalesced read (n contiguous)
    __syncthreads();
    g_wphi[(size_t)(n0 + ty) * EMB + k0 + tx] =
        __float2half(ts[tx][ty]);                          // coalesced write (k contiguous)
}

// ---------------------------------------------------------------------------
// Unified 1-term fp16 GEMM, 3-stage cp.async pipeline, K-chunk 64 (R15-proven).
// C[M,N] = A[M,384] x B[384,N].  6 chunks of 64 over K=384.
// Stage = Ahi(16KB)+Bhi(16KB) = 32KB (swz8); 3 stages = 96KB; 2 CTAs/SM.
// MODE 0: qkv (N=1152; writes q/k/v fp16, q pre-scaled 1/8)
// MODE 1: proj (N=384; adds bias, writes fp32 out)
// ---------------------------------------------------------------------------
#define QST 32768
#define QOFF_AH 0
#define QOFF_BH 16384

template<int MODE>
__global__ __launch_bounds__(256, 2) void gemm_f16(const float* __restrict__ bias,
                                                   float* __restrict__ outp)
{
    extern __shared__ char sm[];
    const uint32_t sb = smem_u32(sm);

    const char* AhiB = (const char*)(MODE == 0 ? g_xhi : g_atthi);
    const char* BhiB = (const char*)(MODE == 0 ? g_wthi : g_wphi);

    const int tid  = threadIdx.x;
    const int wid  = tid >> 5;
    const int lane = tid & 31;
    const int m0   = blockIdx.y * 128;
    const int n0   = blockIdx.x * 128;

    const int wm   = (wid >> 1) * 32;
    const int wn   = (wid & 1) * 64;
    const int a_r  = wm + (lane & 15);
    const int a_u0 = (lane >> 4);
    const int b_r  = wn + ((lane >> 4) & 1) * 8 + (lane & 7);
    const int b_u0 = (lane >> 3) & 1;

    auto issue = [&](int kc) {
        const uint32_t s0 = sb + (kc % 3) * QST;
        const int ko = kc * 128;
        #pragma unroll
        for (int j = 0; j < 4; j++) {
            int idx = tid + 256 * j;
            int r = idx >> 3;
            int u = idx & 7;
            cp16(s0 + QOFF_AH + swz8(r, u), AhiB + (size_t)(m0 + r) * 768 + ko + u * 16);
            cp16(s0 + QOFF_BH + swz8(r, u), BhiB + (size_t)(n0 + r) * 768 + ko + u * 16);
        }
        CP_COMMIT();
    };

    issue(0);
    issue(1);

    float c[2][8][4];
    #pragma unroll
    for (int mt = 0; mt < 2; mt++)
        #pragma unroll
        for (int nt = 0; nt < 8; nt++)
            #pragma unroll
            for (int q = 0; q < 4; q++) c[mt][nt][q] = 0.0f;

    for (int kc = 0; kc < 6; kc++) {
        CP_WAIT_1();
        __syncthreads();
        if (kc + 2 < 6) issue(kc + 2);

        const uint32_t base = sb + (kc % 3) * QST;
        #pragma unroll
        for (int ks = 0; ks < 4; ks++) {
            uint32_t ahi[2][4], bhi[8][2];
            #pragma unroll
            for (int mt = 0; mt < 2; mt++) {
                uint32_t r = a_r + mt * 16;
                uint32_t u = ks * 2 + a_u0;
                ldm4(ahi[mt], base + QOFF_AH + swz8(r, u));
            }
            #pragma unroll
            for (int p = 0; p < 4; p++) {
                uint32_t r = b_r + p * 16;
                uint32_t u = ks * 2 + b_u0;
                uint32_t t4[4];
                ldm4(t4, base + QOFF_BH + swz8(r, u));
                bhi[2 * p][0] = t4[0]; bhi[2 * p][1] = t4[1];
                bhi[2 * p + 1][0] = t4[2]; bhi[2 * p + 1][1] = t4[3];
            }
            #pragma unroll
            for (int mt = 0; mt < 2; mt++)
                #pragma unroll
                for (int nt = 0; nt < 8; nt++)
                    mma_f16(c[mt][nt], ahi[mt], bhi[nt]);
        }
    }

    const int row0 = lane >> 2;
    const int col0 = (lane & 3) * 2;

    if (MODE == 0) {
        const int z = n0 / 384;
        const int nloc = n0 % 384;
        const float scl = (z == 0) ? 0.125f : 1.0f;
        __half* dhi = (z == 0) ? g_qhi : (z == 1) ? g_khi : g_vhi;
        #pragma unroll
        for (int mt = 0; mt < 2; mt++)
            #pragma unroll
            for (int half = 0; half < 2; half++) {
                int m = m0 + wm + mt * 16 + row0 + half * 8;
                int b = m >> 8, t = m & 255;
                #pragma unroll
                for (int nt = 0; nt < 8; nt++) {
                    int n = nloc + wn + nt * 8 + col0;
                    int h = n >> 6, d = n & 63;
                    size_t idx = (((size_t)b * HH + h) * TT + t) * DD + d;
                    *(uint32_t*)(dhi + idx) =
                        pack_h2(c[mt][nt][half * 2] * scl, c[mt][nt][half * 2 + 1] * scl);
                }
            }
    } else {
        #pragma unroll
        for (int mt = 0; mt < 2; mt++)
            #pragma unroll
            for (int half = 0; half < 2; half++) {
                int m = m0 + wm + mt * 16 + row0 + half * 8;
                #pragma unroll
                for (int nt = 0; nt < 8; nt++) {
                    int n = n0 + wn + nt * 8 + col0;
                    float2 val = make_float2(c[mt][nt][half * 2] + bias[n],
                                             c[mt][nt][half * 2 + 1] + bias[n + 1]);
                    *(float2*)(outp + (size_t)m * EMB + n) = val;
                }
            }
    }
}

// ---------------------------------------------------------------------------
// fp16 flash attention: S 1-term, PV 1-term — exact R14/R15-proven version.
// smem: Q 16KB + 2 stages x (K 16KB + V 16KB) = 80KB; 2 CTAs/SM.
// ---------------------------------------------------------------------------
#define AQHI 0
#define AKV0 16384
#define ATT_SMEM 81920

__global__ __launch_bounds__(256, 2) void attn_tc()
{
    extern __shared__ char sm[];
    const uint32_t sb = smem_u32(sm);
    const int qt  = blockIdx.x;
    const int bh  = blockIdx.y;
    const int tid = threadIdx.x;
    const int wid = tid >> 5;
    const int lane = tid & 31;

    const __half* qhi = g_qhi + ((size_t)bh * TT + qt * 128) * DD;
    const __half* khi = g_khi + (size_t)bh * TT * DD;
    const __half* vhi = g_vhi + (size_t)bh * TT * DD;

    #pragma unroll
    for (int j = 0; j < 4; j++) {
        int idx = tid + 256 * j;
        int r = idx >> 3;
        int u = idx & 7;
        cp16(sb + AQHI + swz8(r, u), qhi + (size_t)r * DD + u * 8);
    }
    #pragma unroll
    for (int j = 0; j < 8; j++) {
        int idx = tid + 256 * j;
        int arr = idx >> 10;
        int r = (idx >> 3) & 127;
        int u = idx & 7;
        const __half* src = arr ? vhi : khi;
        cp16(sb + AKV0 + arr * 16384 + swz8(r, u), src + (size_t)r * DD + u * 8);
    }
    CP_COMMIT();
    CP_WAIT_ALL();
    __syncthreads();

    uint32_t qfh[4][4];
    {
        int ar = wid * 16 + (lane & 15);
        #pragma unroll
        for (int kc = 0; kc < 4; kc++) {
            int u = kc * 2 + (lane >> 4);
            ldm4(qfh[kc], sb + AQHI + swz8(ar, u));
        }
    }

    float o[8][4];
    #pragma unroll
    for (int nt = 0; nt < 8; nt++)
        #pragma unroll
        for (int q = 0; q < 4; q++) o[nt][q] = 0.0f;
    float mx[2] = {-1e30f, -1e30f};
    float lsum[2] = {0.0f, 0.0f};

    for (int kt = 0; kt <= qt; kt++) {
        const uint32_t kvb = sb + AKV0 + (kt & 1) * 32768;

        if (kt < qt) {
            #pragma unroll
            for (int j = 0; j < 8; j++) {
                int idx = tid + 256 * j;
                int arr = idx >> 10;
                int r = (idx >> 3) & 127;
                int u = idx & 7;
                const __half* src = arr ? vhi : khi;
                cp16(sb + AKV0 + ((kt + 1) & 1) * 32768 + arr * 16384 + swz8(r, u),
                     src + ((size_t)(kt + 1) * 128 + r) * DD + u * 8);
            }
            CP_COMMIT();
        }

        float s[16][4];
        #pragma unroll
        for (int nt = 0; nt < 16; nt++)
            #pragma unroll
            for (int q = 0; q < 4; q++) s[nt][q] = 0.0f;

        #pragma unroll
        for (int np = 0; np < 8; np++) {
            int br = np * 16 + ((lane >> 4) & 1) * 8 + (lane & 7);
            #pragma unroll
            for (int kc = 0; kc < 4; kc++) {
                int u = kc * 2 + ((lane >> 3) & 1);
                uint32_t th[4];
                ldm4(th, kvb + swz8(br, u));
                uint32_t b0h[2] = {th[0], th[1]}, b1h[2] = {th[2], th[3]};
                mma_f16(s[2 * np], qfh[kc], b0h);
                mma_f16(s[2 * np + 1], qfh[kc], b1h);
            }
        }

        if (kt == qt) {
            #pragma unroll
            for (int nt = 0; nt < 16; nt++)
                #pragma unroll
                for (int q = 0; q < 4; q++) {
                    int col = nt * 8 + (lane & 3) * 2 + (q & 1);
                    int row = wid * 16 + (lane >> 2) + (q >> 1) * 8;
                    if (col > row) s[nt][q] = -1e30f;
                }
        }

        float al[2];
        #pragma unroll
        for (int hf = 0; hf < 2; hf++) {
            float rm = -1e30f;
            #pragma unroll
            for (int nt = 0; nt < 16; nt++)
                rm = fmaxf(rm, fmaxf(s[nt][hf * 2], s[nt][hf * 2 + 1]));
            rm = fmaxf(rm, __shfl_xor_sync(0xffffffffu, rm, 1));
            rm = fmaxf(rm, __shfl_xor_sync(0xffffffffu, rm, 2));
            float mn = fmaxf(mx[hf], rm);
            al[hf] = __expf(mx[hf] - mn);
            mx[hf] = mn;
            float ps = 0.0f;
            #pragma unroll
            for (int nt = 0; nt < 16; nt++) {
                s[nt][hf * 2]     = __expf(s[nt][hf * 2] - mn);
                s[nt][hf * 2 + 1] = __expf(s[nt][hf * 2 + 1] - mn);
                ps += s[nt][hf * 2] + s[nt][hf * 2 + 1];
            }
            ps += __shfl_xor_sync(0xffffffffu, ps, 1);
            ps += __shfl_xor_sync(0xffffffffu, ps, 2);
            lsum[hf] = lsum[hf] * al[hf] + ps;
        }
        #pragma unroll
        for (int nt = 0; nt < 8; nt++) {
            o[nt][0] *= al[0]; o[nt][1] *= al[0];
            o[nt][2] *= al[1]; o[nt][3] *= al[1];
        }

        #pragma unroll
        for (int kc = 0; kc < 8; kc++) {
            uint32_t ah[4];
            ah[0] = pack_h2(s[2 * kc][0], s[2 * kc][1]);
            ah[1] = pack_h2(s[2 * kc][2], s[2 * kc][3]);
            ah[2] = pack_h2(s[2 * kc + 1][0], s[2 * kc + 1][1]);
            ah[3] = pack_h2(s[2 * kc + 1][2], s[2 * kc + 1][3]);

            int vr = kc * 16 + ((lane >> 3) & 1) * 8 + (lane & 7);
            #pragma unroll
            for (int ntp = 0; ntp < 4; ntp++) {
                int u = ntp * 2 + (lane >> 4);
                uint32_t th[4];
                ldm4t(th, kvb + 16384 + swz8(vr, u));
                uint32_t b0h[2] = {th[0], th[1]}, b1h[2] = {th[2], th[3]};
                mma_f16(o[2 * ntp], ah, b0h);
                mma_f16(o[2 * ntp + 1], ah, b1h);
            }
        }

        if (kt < qt) {
            CP_WAIT_ALL();
            __syncthreads();
        }
    }

    const int b = bh / HH, h = bh % HH;
    #pragma unroll
    for (int hf = 0; hf < 2; hf++) {
        float inv = 1.0f / lsum[hf];
        int t = qt * 128 + wid * 16 + (lane >> 2) + hf * 8;
        size_t rowb = ((size_t)b * TT + t) * EMB + h * 64 + (lane & 3) * 2;
        #pragma unroll
        for (int nt = 0; nt < 8; nt++)
            *(uint32_t*)(g_atthi + rowb + nt * 8) =
                pack_h2(o[nt][hf * 2] * inv, o[nt][hf * 2 + 1] * inv);
    }
}

// ---------------------------------------------------------------------------
extern "C" void kernel_launch(void* const* d_in, const int* in_sizes, int n_in,
                              void* d_out, int out_size)
{
    const float* x      = (const float*)d_in[0];
    const float* wq     = (const float*)d_in[1];
    const float* wk     = (const float*)d_in[2];
    const float* wv     = (const float*)d_in[3];
    const float* w_proj = (const float*)d_in[4];
    const float* b_proj = (const float*)d_in[5];
    float* out = (float*)d_out;

    cudaFuncSetAttribute(gemm_f16<0>, cudaFuncAttributeMaxDynamicSharedMemorySize, 3 * QST);
    cudaFuncSetAttribute(gemm_f16<1>, cudaFuncAttributeMaxDynamicSharedMemorySize, 3 * QST);
    cudaFuncSetAttribute(attn_tc, cudaFuncAttributeMaxDynamicSharedMemorySize, ATT_SMEM);

    prep_x<<<(NX4 + 255) / 256, 256>>>(x);
    prep_wqkv<<<dim3(EMB / 32, DD / 32, 3 * HH), dim3(32, 32)>>>(wq, wk, wv);
    prep_wpk<<<dim3(EMB / 32, EMB / 32), dim3(32, 32)>>>(w_proj);

    gemm_f16<0><<<dim3(1152 / 128, BT / 128), 256, 3 * QST>>>(nullptr, nullptr);
    attn_tc<<<dim3(TT / 128, BB * HH), 256, ATT_SMEM>>>();
    gemm_f16<1><<<dim3(EMB / 128, BT / 128), 256, 3 * QST>>>(b_proj, out);
}